// round 1
// baseline (speedup 1.0000x reference)
#include <cuda_runtime.h>
#include <cuda_bf16.h>
#include <math_constants.h>

#define N_TOKENS   8192
#define QUANT_DIM  8192
#define OUTPUT_DIM 1024

// Scratch (allocations are forbidden; __device__ globals are the sanctioned path)
__device__ int   g_idx[N_TOKENS];
__device__ float g_Wt[(size_t)QUANT_DIM * OUTPUT_DIM];   // W transposed: [8192, 1024]

// ---------------------------------------------------------------------------
// Kernel 1: per-row argmax of x [N_TOKENS, QUANT_DIM]
// One block per row, 256 threads, float4 loads. First-index tie-break to
// match jnp.argmax semantics.
// ---------------------------------------------------------------------------
__global__ __launch_bounds__(256) void argmax_rows_kernel(
    const float* __restrict__ x, int* __restrict__ idx_out)
{
    const int row = blockIdx.x;
    const float4* __restrict__ xr =
        reinterpret_cast<const float4*>(x + (size_t)row * QUANT_DIM);

    float best = -CUDART_INF_F;
    int   bidx = 0;

    // 8192 floats = 2048 float4; 256 threads -> 8 iterations
    #pragma unroll
    for (int it = 0; it < 8; ++it) {
        const int i = threadIdx.x + it * 256;
        const float4 v = xr[i];
        const int base = i * 4;
        if (v.x > best) { best = v.x; bidx = base + 0; }
        if (v.y > best) { best = v.y; bidx = base + 1; }
        if (v.z > best) { best = v.z; bidx = base + 2; }
        if (v.w > best) { best = v.w; bidx = base + 3; }
    }

    // warp reduce (value desc, index asc on tie)
    #pragma unroll
    for (int off = 16; off > 0; off >>= 1) {
        float ov = __shfl_down_sync(0xFFFFFFFFu, best, off);
        int   oi = __shfl_down_sync(0xFFFFFFFFu, bidx, off);
        if (ov > best || (ov == best && oi < bidx)) { best = ov; bidx = oi; }
    }

    __shared__ float s_val[8];
    __shared__ int   s_idx[8];
    const int lane = threadIdx.x & 31;
    const int warp = threadIdx.x >> 5;
    if (lane == 0) { s_val[warp] = best; s_idx[warp] = bidx; }
    __syncthreads();

    if (warp == 0) {
        best = (lane < 8) ? s_val[lane] : -CUDART_INF_F;
        bidx = (lane < 8) ? s_idx[lane] : 0x7FFFFFFF;
        #pragma unroll
        for (int off = 4; off > 0; off >>= 1) {
            float ov = __shfl_down_sync(0xFFFFFFFFu, best, off);
            int   oi = __shfl_down_sync(0xFFFFFFFFu, bidx, off);
            if (ov > best || (ov == best && oi < bidx)) { best = ov; bidx = oi; }
        }
        if (lane == 0) idx_out[row] = bidx;
    }
}

// ---------------------------------------------------------------------------
// Kernel 2: transpose W [OUTPUT_DIM, QUANT_DIM] -> Wt [QUANT_DIM, OUTPUT_DIM]
// 32x32 tile via smem (33-wide to kill bank conflicts). Block (32,8).
// ---------------------------------------------------------------------------
__global__ __launch_bounds__(256) void transpose_kernel(
    const float* __restrict__ W, float* __restrict__ Wt)
{
    __shared__ float tile[32][33];

    const int col = blockIdx.x * 32 + threadIdx.x;  // column in W (0..8191)
    const int row = blockIdx.y * 32 + threadIdx.y;  // row in W    (0..1023)

    #pragma unroll
    for (int j = 0; j < 32; j += 8)
        tile[threadIdx.y + j][threadIdx.x] = W[(size_t)(row + j) * QUANT_DIM + col];

    __syncthreads();

    const int tcol = blockIdx.y * 32 + threadIdx.x; // column in Wt (0..1023)
    const int trow = blockIdx.x * 32 + threadIdx.y; // row in Wt    (0..8191)

    #pragma unroll
    for (int j = 0; j < 32; j += 8)
        Wt[(size_t)(trow + j) * OUTPUT_DIM + tcol] = tile[threadIdx.x][threadIdx.y + j];
}

// ---------------------------------------------------------------------------
// Kernel 3: gather rows of Wt by idx -> out. Contiguous 4KB copy per token.
// One block per token, 256 threads x float4 = 1024 floats.
// ---------------------------------------------------------------------------
__global__ __launch_bounds__(256) void gather_rows_kernel(
    const float* __restrict__ Wt, const int* __restrict__ idx,
    float* __restrict__ out)
{
    const int n = blockIdx.x;
    const int r = idx[n];  // uniform per-block load (broadcast via L1/const path)
    const float4* __restrict__ src =
        reinterpret_cast<const float4*>(Wt + (size_t)r * OUTPUT_DIM);
    float4* __restrict__ dst =
        reinterpret_cast<float4*>(out + (size_t)n * OUTPUT_DIM);
    dst[threadIdx.x] = src[threadIdx.x];
}

// ---------------------------------------------------------------------------
extern "C" void kernel_launch(void* const* d_in, const int* in_sizes, int n_in,
                              void* d_out, int out_size)
{
    const float* x = (const float*)d_in[0];   // [8192, 8192] fp32
    const float* W = (const float*)d_in[1];   // [1024, 8192] fp32
    float* out = (float*)d_out;               // [8192, 1024] fp32

    int*   idx_dev;
    float* Wt_dev;
    cudaGetSymbolAddress((void**)&idx_dev, g_idx);
    cudaGetSymbolAddress((void**)&Wt_dev,  g_Wt);

    // 1) argmax per token
    argmax_rows_kernel<<<N_TOKENS, 256>>>(x, idx_dev);

    // 2) transpose W -> Wt (independent of argmax, same stream = fine)
    dim3 tgrid(QUANT_DIM / 32, OUTPUT_DIM / 32);
    transpose_kernel<<<tgrid, dim3(32, 8)>>>(W, Wt_dev);

    // 3) gather
    gather_rows_kernel<<<N_TOKENS, 256>>>(Wt_dev, idx_dev, out);
}

// round 2
// speedup vs baseline: 1.1384x; 1.1384x over previous
#include <cuda_runtime.h>
#include <cuda_bf16.h>
#include <math_constants.h>

#define N_TOKENS   8192
#define QUANT_DIM  8192
#define OUTPUT_DIM 1024

// Transpose tiling: 32x32 tiles
#define T_BX (QUANT_DIM / 32)    // 256 tiles along quant dim
#define T_BY (OUTPUT_DIM / 32)   // 32 tiles along output dim
#define TRANS_BLOCKS (T_BX * T_BY)   // 8192

// Scratch (__device__ globals: the sanctioned allocation-free path)
__device__ int   g_idx[N_TOKENS];
__device__ float g_Wt[(size_t)QUANT_DIM * OUTPUT_DIM];   // W^T: [8192, 1024]

// ---------------------------------------------------------------------------
// Fused kernel: blocks [0, TRANS_BLOCKS) transpose W -> Wt,
//               blocks [TRANS_BLOCKS, TRANS_BLOCKS + N_TOKENS) do row argmax.
// Independent work; fusing removes a launch gap and overlaps the argmax tail.
// x is read with .cs (evict-first) so Wt stays resident in L2 for the gather.
// ---------------------------------------------------------------------------
__global__ __launch_bounds__(256) void fused_trans_argmax_kernel(
    const float* __restrict__ x, const float* __restrict__ W,
    float* __restrict__ Wt, int* __restrict__ idx_out)
{
    __shared__ float smem[32 * 33];   // transpose tile (33 stride: no conflicts)

    if (blockIdx.x < TRANS_BLOCKS) {
        // ----- transpose tile -----
        const int bid = blockIdx.x;
        const int bx = bid & (T_BX - 1);   // tile along quant dim (cols of W)
        const int by = bid >> 8;           // tile along output dim (rows of W)
        const int tx = threadIdx.x & 31;
        const int ty = threadIdx.x >> 5;   // 0..7

        const int col = bx * 32 + tx;      // column in W
        const int row = by * 32 + ty;      // row in W

        #pragma unroll
        for (int j = 0; j < 32; j += 8)
            smem[(ty + j) * 33 + tx] = W[(size_t)(row + j) * QUANT_DIM + col];

        __syncthreads();

        const int tcol = by * 32 + tx;     // column in Wt (0..1023)
        const int trow = bx * 32 + ty;     // row in Wt    (0..8191)

        #pragma unroll
        for (int j = 0; j < 32; j += 8)
            Wt[(size_t)(trow + j) * OUTPUT_DIM + tcol] = smem[tx * 33 + (ty + j)];
        return;
    }

    // ----- argmax over one row of x -----
    const int row = blockIdx.x - TRANS_BLOCKS;
    const float4* __restrict__ xr =
        reinterpret_cast<const float4*>(x + (size_t)row * QUANT_DIM);

    float best = -CUDART_INF_F;
    int   bidx = 0;

    // 8192 floats = 2048 float4; 256 threads -> 8 iterations, index-increasing
    #pragma unroll
    for (int it = 0; it < 8; ++it) {
        const int i = threadIdx.x + it * 256;
        const float4 v = __ldcs(&xr[i]);          // streaming: don't evict Wt
        const float vm = fmaxf(fmaxf(v.x, v.y), fmaxf(v.z, v.w));
        if (vm > best) {                           // rare after warmup
            best = vm;
            const int base = i * 4;
            bidx = (v.x == vm) ? base
                 : (v.y == vm) ? base + 1
                 : (v.z == vm) ? base + 2
                 :               base + 3;         // first-equal = first index
        }
    }

    // warp reduce: value desc, index asc on exact tie (jnp.argmax semantics)
    #pragma unroll
    for (int off = 16; off > 0; off >>= 1) {
        float ov = __shfl_down_sync(0xFFFFFFFFu, best, off);
        int   oi = __shfl_down_sync(0xFFFFFFFFu, bidx, off);
        if (ov > best || (ov == best && oi < bidx)) { best = ov; bidx = oi; }
    }

    __shared__ float s_val[8];
    __shared__ int   s_idx[8];
    const int lane = threadIdx.x & 31;
    const int warp = threadIdx.x >> 5;
    if (lane == 0) { s_val[warp] = best; s_idx[warp] = bidx; }
    __syncthreads();

    if (warp == 0) {
        best = (lane < 8) ? s_val[lane] : -CUDART_INF_F;
        bidx = (lane < 8) ? s_idx[lane] : 0x7FFFFFFF;
        #pragma unroll
        for (int off = 4; off > 0; off >>= 1) {
            float ov = __shfl_down_sync(0xFFFFFFFFu, best, off);
            int   oi = __shfl_down_sync(0xFFFFFFFFu, bidx, off);
            if (ov > best || (ov == best && oi < bidx)) { best = ov; bidx = oi; }
        }
        if (lane == 0) idx_out[row] = bidx;
    }
}

// ---------------------------------------------------------------------------
// Gather: out[n][:] = Wt[idx[n]][:].  Contiguous 4KB copy per token.
// Wt reads should hit L2 (x was streamed .cs); out writes streamed .cs.
// ---------------------------------------------------------------------------
__global__ __launch_bounds__(256) void gather_rows_kernel(
    const float* __restrict__ Wt, const int* __restrict__ idx,
    float* __restrict__ out)
{
    const int n = blockIdx.x;
    const int r = __ldg(&idx[n]);   // uniform per-block
    const float4* __restrict__ src =
        reinterpret_cast<const float4*>(Wt + (size_t)r * OUTPUT_DIM);
    float4* __restrict__ dst =
        reinterpret_cast<float4*>(out + (size_t)n * OUTPUT_DIM);
    const float4 v = src[threadIdx.x];
    __stcs(&dst[threadIdx.x], v);   // never re-read: evict-first
}

// ---------------------------------------------------------------------------
extern "C" void kernel_launch(void* const* d_in, const int* in_sizes, int n_in,
                              void* d_out, int out_size)
{
    const float* x = (const float*)d_in[0];   // [8192, 8192] fp32
    const float* W = (const float*)d_in[1];   // [1024, 8192] fp32
    float* out = (float*)d_out;               // [8192, 1024] fp32

    int*   idx_dev;
    float* Wt_dev;
    cudaGetSymbolAddress((void**)&idx_dev, g_idx);
    cudaGetSymbolAddress((void**)&Wt_dev,  g_Wt);

    fused_trans_argmax_kernel<<<TRANS_BLOCKS + N_TOKENS, 256>>>(
        x, W, Wt_dev, idx_dev);

    gather_rows_kernel<<<N_TOKENS, 256>>>(Wt_dev, idx_dev, out);
}